// round 1
// baseline (speedup 1.0000x reference)
#include <cuda_runtime.h>
#include <cuda_bf16.h>
#include <cstdio>

// Problem constants
#define BB 8
#define IC 1024
#define OC 512
#define HH 64
#define WW 48
#define HW 3072            // H*W
#define AA 9
#define SZ_PROB (8*18*3072)   // 442368
#define SZ_BBOX (8*36*3072)   // 884736
#define OUT_LCLS (SZ_PROB + SZ_BBOX)     // 1327104
#define OUT_LBOX (SZ_PROB + SZ_BBOX + 1) // 1327105

// -------- device-global scratch (no allocations allowed) --------
__device__ float g_conv1[(size_t)BB*OC*HW];   // 12.58M floats
__device__ float g_wt[(size_t)IC*9*OC];       // transposed conv weights [ic*9+k][oc]
__device__ float g_wh[512*56];                // transposed head weights [ic][56] (18 cls + 36 bbox + 2 pad)
__device__ float g_cls[SZ_PROB];              // raw cls scores
__device__ float g_acc[3];                    // nll_sum, valid_cnt, box_sum

// -------- f32x2 helpers (sm_103a packed fp32) --------
__device__ __forceinline__ unsigned long long pk1(float x) {
  unsigned long long r; unsigned int u = __float_as_uint(x);
  asm("mov.b64 %0, {%1, %1};" : "=l"(r) : "r"(u));
  return r;
}
__device__ __forceinline__ unsigned long long pk2(float lo, float hi) {
  unsigned long long r;
  asm("mov.b64 %0, {%1, %2};" : "=l"(r) : "r"(__float_as_uint(lo)), "r"(__float_as_uint(hi)));
  return r;
}
__device__ __forceinline__ void upk(unsigned long long v, float& lo, float& hi) {
  unsigned int a, b;
  asm("mov.b64 {%0, %1}, %2;" : "=r"(a), "=r"(b) : "l"(v));
  lo = __uint_as_float(a); hi = __uint_as_float(b);
}
__device__ __forceinline__ void fma2(unsigned long long& acc, unsigned long long a, unsigned long long b) {
  asm("fma.rn.f32x2 %0, %1, %2, %0;" : "+l"(acc) : "l"(a), "l"(b));
}

// -------- block reduce --------
__device__ __forceinline__ float blockReduceSum(float v) {
  __shared__ float sh[32];
  __syncthreads();
  #pragma unroll
  for (int o = 16; o; o >>= 1) v += __shfl_down_sync(0xffffffffu, v, o);
  int lane = threadIdx.x & 31, wid = threadIdx.x >> 5;
  if (lane == 0) sh[wid] = v;
  __syncthreads();
  int nw = blockDim.x >> 5;
  v = (threadIdx.x < (unsigned)nw) ? sh[threadIdx.x] : 0.f;
  if (wid == 0) {
    #pragma unroll
    for (int o = 16; o; o >>= 1) v += __shfl_down_sync(0xffffffffu, v, o);
  }
  return v;
}

// -------- K0: zero accumulators --------
__global__ void k_zero() {
  if (threadIdx.x < 3) g_acc[threadIdx.x] = 0.f;
}

// -------- K: transpose conv weights  W[oc][ic][3][3] -> g_wt[(ic*9+k)][oc] --------
__global__ void k_transpose_w(const float* __restrict__ Wc) {
  int i = blockIdx.x * 256 + threadIdx.x;          // 9216*512 total
  if (i >= 9216 * 512) return;
  int oc = i & 511;
  int row = i >> 9;                                // ic*9 + k
  g_wt[i] = Wc[(size_t)oc * 9216 + row];
}

// -------- K: transpose head weights -> g_wh[ic][56] --------
__global__ void k_transpose_h(const float* __restrict__ Wcls, const float* __restrict__ Wbb) {
  int i = blockIdx.x * 256 + threadIdx.x;          // 512*56
  if (i >= 512 * 56) return;
  int ic = i / 56, ch = i - ic * 56;
  float v = 0.f;
  if (ch < 18) v = Wcls[ch * 512 + ic];
  else if (ch < 54) v = Wbb[(ch - 18) * 512 + ic];
  g_wh[i] = v;
}

// -------- K1: 3x3 conv + bias + relu  (implicit GEMM, f32x2 over oc-pairs) --------
// block: 128 oc x (2 rows x 48 w), 256 threads, ic-chunks of 8
__global__ void __launch_bounds__(256, 2) k_conv(const float* __restrict__ x,
                                                 const float* __restrict__ bconv) {
  __shared__ __align__(16) float sW[72 * 128];   // [ic(8)*9+k][128 oc]
  __shared__ float sX[8 * 4 * 50];               // [ic][4 rows][50 cols (w=-1..48)]

  const int b   = blockIdx.z;
  const int h0  = blockIdx.y * 2;
  const int oc0 = blockIdx.x * 128;
  const int tid = threadIdx.x;
  const int wg  = tid & 15;        // 16 w-groups
  const int og  = tid >> 4;        // 16 oc-groups of 8
  const int w0  = wg * 3;
  const int ocT = og * 8;

  unsigned long long acc[4][2][3];
  #pragma unroll
  for (int j = 0; j < 4; j++) {
    unsigned long long bp = pk2(bconv[oc0 + ocT + 2*j], bconv[oc0 + ocT + 2*j + 1]);
    #pragma unroll
    for (int r = 0; r < 2; r++)
      #pragma unroll
      for (int c = 0; c < 3; c++)
        acc[j][r][c] = bp;
  }

  const float* xb = x + (size_t)b * IC * HW;

  #pragma unroll 1
  for (int ic0 = 0; ic0 < IC; ic0 += 8) {
    __syncthreads();
    // stage weights: 72 rows x 128 oc (fully coalesced float4 copy)
    {
      const float4* src = (const float4*)(g_wt + (size_t)ic0 * 9 * 512 + oc0);
      float4* dst = (float4*)sW;
      #pragma unroll
      for (int i = tid; i < 72 * 32; i += 256) {
        int r = i >> 5, c = i & 31;
        dst[i] = src[r * 128 + c];
      }
    }
    // stage inputs: 8 ic x 4 rows x 50 cols (zero-padded borders)
    #pragma unroll 1
    for (int i = tid; i < 8 * 200; i += 256) {
      int ic  = i / 200;
      int rem = i - ic * 200;
      int r   = rem / 50;
      int col = rem - r * 50;
      int gh = h0 - 1 + r;
      int gw = col - 1;
      float v = 0.f;
      if ((unsigned)gh < 64u && (unsigned)gw < 48u)
        v = xb[(size_t)(ic0 + ic) * HW + gh * 48 + gw];
      sX[i] = v;
    }
    __syncthreads();

    #pragma unroll 1
    for (int ic = 0; ic < 8; ic++) {
      #pragma unroll
      for (int kh = 0; kh < 3; kh++) {
        unsigned long long px[2][5];
        #pragma unroll
        for (int r = 0; r < 2; r++)
          #pragma unroll
          for (int c = 0; c < 5; c++)
            px[r][c] = pk1(sX[(ic * 4 + kh + r) * 50 + w0 + c]);
        #pragma unroll
        for (int kw = 0; kw < 3; kw++) {
          const unsigned long long* wp =
              (const unsigned long long*)(sW + ((ic * 9 + kh * 3 + kw) << 7) + ocT);
          unsigned long long wq0 = wp[0], wq1 = wp[1], wq2 = wp[2], wq3 = wp[3];
          #pragma unroll
          for (int r = 0; r < 2; r++) {
            #pragma unroll
            for (int c = 0; c < 3; c++) {
              unsigned long long xv = px[r][c + kw];
              fma2(acc[0][r][c], wq0, xv);
              fma2(acc[1][r][c], wq1, xv);
              fma2(acc[2][r][c], wq2, xv);
              fma2(acc[3][r][c], wq3, xv);
            }
          }
        }
      }
    }
  }

  // epilogue: relu + store
  float* outp = g_conv1 + ((size_t)b * OC + oc0 + ocT) * HW + h0 * 48 + w0;
  #pragma unroll
  for (int j = 0; j < 4; j++) {
    #pragma unroll
    for (int r = 0; r < 2; r++) {
      #pragma unroll
      for (int c = 0; c < 3; c++) {
        float lo, hi; upk(acc[j][r][c], lo, hi);
        size_t base = (size_t)(2 * j) * HW + r * 48 + c;
        outp[base]       = fmaxf(lo, 0.f);
        outp[base + HW]  = fmaxf(hi, 0.f);
      }
    }
  }
}

// -------- K2: 1x1 heads (cls 18 + bbox 36 fused as 54-ch GEMM) --------
// block: 128 spatial x 54 ch, 256 threads (2 halves of 28 ch), ic-chunks of 64
__global__ void __launch_bounds__(256) k_heads(const float* __restrict__ bcls,
                                               const float* __restrict__ bbb,
                                               float* __restrict__ out) {
  __shared__ __align__(16) float sx[64 * 128];
  __shared__ __align__(16) float sw[64 * 56];
  const int t   = blockIdx.x;          // 0..191
  const int b   = t / 24;
  const int sp0 = (t % 24) * 128;
  const int tid = threadIdx.x;
  const int sp   = tid & 127;
  const int half = tid >> 7;

  float accv[28];
  #pragma unroll
  for (int j = 0; j < 28; j++) accv[j] = 0.f;

  #pragma unroll 1
  for (int ic0 = 0; ic0 < 512; ic0 += 64) {
    __syncthreads();
    {
      float4* dst = (float4*)sx;
      #pragma unroll 1
      for (int i = tid; i < 2048; i += 256) {
        int ic = i >> 5, c = i & 31;
        dst[i] = *(const float4*)(g_conv1 + (size_t)(b * 512 + ic0 + ic) * HW + sp0 + c * 4);
      }
      float4* dw = (float4*)sw;
      const float4* srw = (const float4*)(g_wh + ic0 * 56);
      #pragma unroll 1
      for (int i = tid; i < 896; i += 256) dw[i] = srw[i];
    }
    __syncthreads();
    #pragma unroll 1
    for (int ic = 0; ic < 64; ic++) {
      float xv = sx[ic * 128 + sp];
      const float* wr = sw + ic * 56 + half * 28;
      #pragma unroll
      for (int j = 0; j < 28; j++) accv[j] = fmaf(xv, wr[j], accv[j]);
    }
  }

  const int chb = half * 28;
  #pragma unroll
  for (int j = 0; j < 28; j++) {
    int ch = chb + j;
    if (ch < 54) {
      float bias = (ch < 18) ? bcls[ch] : bbb[ch - 18];
      float v = accv[j] + bias;
      if (ch < 18) g_cls[(size_t)(b * 18 + ch) * HW + sp0 + sp] = v;
      else         out[SZ_PROB + (size_t)(b * 36 + (ch - 18)) * HW + sp0 + sp] = v;
    }
  }
}

// -------- K3: paired softmax -> prob, + NLL cls loss --------
__global__ void __launch_bounds__(256) k_cls(const int* __restrict__ label,
                                             float* __restrict__ out) {
  int idx = blockIdx.x * 256 + threadIdx.x;   // < 8*9*3072 = 221184
  float nll = 0.f, cnt = 0.f;
  if (idx < BB * AA * HW) {
    int b   = idx / (AA * HW);
    int rem = idx - b * (AA * HW);
    int a   = rem / HW;
    int s   = rem - a * HW;
    float l0 = g_cls[(size_t)(b * 18 + a) * HW + s];
    float l1 = g_cls[(size_t)(b * 18 + a + 9) * HW + s];
    float m  = fmaxf(l0, l1);
    float e0 = expf(l0 - m), e1 = expf(l1 - m);
    float sum = e0 + e1;
    float inv = 1.f / sum;
    out[(size_t)(b * 18 + a) * HW + s]     = e0 * inv;
    out[(size_t)(b * 18 + a + 9) * HW + s] = e1 * inv;
    int lb = label[idx];
    if (lb >= 0) {
      float chosen = lb ? l1 : l0;
      nll = -(chosen - m - logf(sum));
      cnt = 1.f;
    }
  }
  float s1 = blockReduceSum(nll);
  if (threadIdx.x == 0) atomicAdd(&g_acc[0], s1);
  float s2 = blockReduceSum(cnt);
  if (threadIdx.x == 0) atomicAdd(&g_acc[1], s2);
}

// -------- K4: smooth-L1 box loss --------
__global__ void __launch_bounds__(256) k_box(const float* __restrict__ tgt,
                                             const float* __restrict__ iw,
                                             const float* __restrict__ ow,
                                             const float* __restrict__ bbox) {
  int i = blockIdx.x * 256 + threadIdx.x;     // < 884736
  float v = 0.f;
  if (i < SZ_BBOX) {
    float d  = iw[i] * (bbox[i] - tgt[i]);
    float ad = fabsf(d);
    float l  = (ad < (1.f / 9.f)) ? d * d * 4.5f : (ad - (1.f / 18.f));
    v = ow[i] * l;
  }
  float s = blockReduceSum(v);
  if (threadIdx.x == 0) atomicAdd(&g_acc[2], s);
}

// -------- K5: finalize scalars --------
__global__ void k_fin(float* out) {
  out[OUT_LCLS] = g_acc[0] / fmaxf(g_acc[1], 1.f);
  out[OUT_LBOX] = g_acc[2] * 0.125f;
}

extern "C" void kernel_launch(void* const* d_in, const int* in_sizes, int n_in,
                              void* d_out, int out_size) {
  const float* base_feat = (const float*)d_in[0];
  const float* W_conv    = (const float*)d_in[1];
  const float* b_conv    = (const float*)d_in[2];
  const float* W_cls     = (const float*)d_in[3];
  const float* b_cls     = (const float*)d_in[4];
  const float* W_bbox    = (const float*)d_in[5];
  const float* b_bbox    = (const float*)d_in[6];
  const int*   rpn_label = (const int*)d_in[7];
  const float* tgt       = (const float*)d_in[8];
  const float* iw        = (const float*)d_in[9];
  const float* ow        = (const float*)d_in[10];
  float* out = (float*)d_out;

  k_zero<<<1, 32>>>();
  k_transpose_w<<<(9216 * 512 + 255) / 256, 256>>>(W_conv);
  k_transpose_h<<<(512 * 56 + 255) / 256, 256>>>(W_cls, W_bbox);
  k_conv<<<dim3(4, 32, 8), 256>>>(base_feat, b_conv);
  k_heads<<<192, 256>>>(b_cls, b_bbox, out);
  k_cls<<<(BB * AA * HW + 255) / 256, 256>>>(rpn_label, out);
  k_box<<<(SZ_BBOX + 255) / 256, 256>>>(tgt, iw, ow, out + SZ_PROB);
  k_fin<<<1, 1>>>(out);
}